// round 6
// baseline (speedup 1.0000x reference)
#include <cuda_runtime.h>
#include <math.h>

// Problem constants (fixed shapes for HoughSplitLoss_12884901888574)
#define B_   32
#define L_   6
#define A_   1024
#define R_   1024
#define RAD  5
#define WIN  11                   // 2*RAD+1
#define NWIN (WIN * WIN)          // 121
#define NELEM (1024u * 1024u)     // per-batch plane elements
#define TOTAL_ELEMS ((long long)B_ * A_ * R_)  // 33554432

#define NTHR 1024                 // 32 warps; warp w owns batch w

__device__ __forceinline__ float sigmoidf_(float x) {
    // Fast sigmoid: error far inside the 1e-3 budget.
    return __frcp_rn(1.0f + __expf(-x));
}

// ---------------------------------------------------------------------------
// ONE block, 32 warps, warp = batch. No global atomics, no fences, no device
// scratch, no cross-block rendezvous -> the kernel is just:
//   points load -> one sort per warp -> 6 x (8-wide MLP gather) -> one warp
//   reduce -> 32 smem partials -> thread 0 fixed-tree sum -> store.
// Fully deterministic (fixed reduction tree, single block).
// ---------------------------------------------------------------------------
__global__ __launch_bounds__(NTHR)
void loss_fused(const float* __restrict__ pre_hough,
                const float* __restrict__ gt_hough,
                const int*   __restrict__ in_pre_points,
                const int*   __restrict__ gt_points,
                float*       __restrict__ out)
{
    __shared__ float  s_warp[32];
    __shared__ int    s_fb;
    __shared__ double s_red[256];

    const int tid  = threadIdx.x;
    const int warp = tid >> 5;      // = batch b
    const int lane = tid & 31;
    const int b    = warp;

    // ---- Per-batch point prep, redundantly in every lane (broadcast loads,
    //      identical sort -> no serialization, no shared round-trip) ----
    int px[L_], py[L_];
    int gx[L_], gy[L_];
    {
        const int4* pp = (const int4*)(in_pre_points + b * (L_ * 2));
        const int4* gg = (const int4*)(gt_points     + b * (L_ * 2));
        const int4 v0 = pp[0], v1 = pp[1], v2 = pp[2];
        const int4 w0 = gg[0], w1 = gg[1], w2 = gg[2];
        px[0]=v0.x; py[0]=v0.y; px[1]=v0.z; py[1]=v0.w;
        px[2]=v1.x; py[2]=v1.y; px[3]=v1.z; py[3]=v1.w;
        px[4]=v2.x; py[4]=v2.y; px[5]=v2.z; py[5]=v2.w;
        gx[0]=w0.x; gy[0]=w0.y; gx[1]=w0.z; gy[1]=w0.w;
        gx[2]=w1.x; gy[2]=w1.y; gx[3]=w1.z; gy[3]=w1.w;
        gx[4]=w2.x; gy[4]=w2.y; gx[5]=w2.z; gy[5]=w2.w;

        long long key[L_];
        #pragma unroll
        for (int i = 0; i < L_; ++i)
            key[i] = (px[i] < 0) ? (1LL << 30)
                                 : (long long)px[i] * 10000LL + (long long)py[i];
        // Stable insertion sort (matches stable argsort; ties outcome-neutral).
        #pragma unroll
        for (int i = 1; i < L_; ++i) {
            long long kk = key[i];
            int kx = px[i], ky = py[i];
            int j = i - 1;
            while (j >= 0 && key[j] > kk) {
                key[j + 1] = key[j]; px[j + 1] = px[j]; py[j + 1] = py[j];
                --j;
            }
            key[j + 1] = kk; px[j + 1] = kx; py[j + 1] = ky;
        }
    }

    // ---- 6 points per warp; per point: 4 independent LDG pairs per lane
    //      (MLP=8). Weight distributes into per-cell terms, so we keep ONE
    //      per-lane accumulator and do a single warp reduce at the end. ----
    const float* __restrict__ phb = pre_hough + (size_t)b * NELEM;
    const float* __restrict__ gpb = gt_hough  + (size_t)b * NELEM;

    float acc = 0.0f;
    #pragma unroll
    for (int l = 0; l < L_; ++l) {
        const bool use_gt   = (gx[l] >= 0);
        const bool one_inv  = (px[l] < 0) || (gx[l] < 0);
        const bool both_inv = (px[l] < 0) && (gx[l] < 0);
        const int X = use_gt ? gx[l] : px[l];
        const int Y = use_gt ? gy[l] : py[l];
        const float W = both_inv ? 0.0f
                                 : (one_inv ? 10.0f : 1.0f) / (float)(RAD * RAD);

        float vp[4], vg[4];
        bool  ok[4];
        #pragma unroll
        for (int it = 0; it < 4; ++it) {
            const int idx = lane + it * 32;
            const int di  = idx / WIN - RAD;
            const int dj  = idx % WIN - RAD;
            const int xi  = X + di;
            const int yi  = Y + dj;
            ok[it] = (idx < NWIN) & (xi >= 0) & (xi < R_) & (yi >= 0) & (yi < A_);
            const size_t off = (size_t)(ok[it] ? xi : 0) * R_ + (ok[it] ? yi : 0);
            vp[it] = phb[off];      // batched: all 8 loads in flight together
            vg[it] = gpb[off];
        }
        float ps = 0.0f;
        #pragma unroll
        for (int it = 0; it < 4; ++it)
            if (ok[it]) ps += fabsf(sigmoidf_(vp[it]) - vg[it]);
        acc += ps * W;
    }

    // ---- One warp reduce; 32 partials; thread 0 fixed-tree sum ----
    #pragma unroll
    for (int off = 16; off > 0; off >>= 1)
        acc += __shfl_down_sync(0xffffffffu, acc, off);
    if (lane == 0) s_warp[warp] = acc;
    __syncthreads();

    if (tid == 0) {
        float total = 0.0f;
        #pragma unroll
        for (int w = 0; w < 32; ++w) total += s_warp[w];
        if (total != 0.0f) {
            out[0] = total / (float)B_;
            s_fb = 0;
        } else {
            s_fb = 1;
        }
    }
    __syncthreads();

    // ---- Fallback: total == 0 (semantically required; never on this data).
    //      First 256 threads grid-stride the full plane. ----
    if (s_fb) {
        if (tid < 256) {
            double d = 0.0;
            for (long long i = tid; i < TOTAL_ELEMS; i += 256)
                d += (double)fabsf(1.0f / (1.0f + expf(-pre_hough[i])) - gt_hough[i]);
            s_red[tid] = d;
        }
        __syncthreads();
        if (tid < 256) {
            for (int off = 128; off > 0; off >>= 1) {
                if (tid < off) s_red[tid] += s_red[tid + off];
                __syncthreads();
            }
            if (tid == 0)
                out[0] = (float)(s_red[0] / (double)TOTAL_ELEMS);
        }
    }
}

// ---------------------------------------------------------------------------
extern "C" void kernel_launch(void* const* d_in, const int* in_sizes, int n_in,
                              void* d_out, int out_size)
{
    const float* pre_hough     = (const float*)d_in[0];
    const float* gt_hough      = (const float*)d_in[1];
    const int*   in_pre_points = (const int*)d_in[2];
    const int*   gt_points     = (const int*)d_in[3];
    float*       out           = (float*)d_out;

    loss_fused<<<1, NTHR>>>(pre_hough, gt_hough, in_pre_points, gt_points, out);
}

// round 7
// speedup vs baseline: 3.1790x; 3.1790x over previous
#include <cuda_runtime.h>
#include <math.h>

// Problem constants (fixed shapes for HoughSplitLoss_12884901888574)
#define B_   32
#define L_   6
#define A_   1024
#define R_   1024
#define NPTS (B_ * L_)            // 192
#define RAD  5
#define WIN  11                   // 2*RAD+1
#define NWIN (WIN * WIN)          // 121
#define NELEM (1024u * 1024u)     // per-batch plane elements
#define TOTAL_ELEMS ((long long)B_ * A_ * R_)  // 33554432

#define NTHR   256                // 8 warps/block, one point per warp
#define WARPS  (NTHR / 32)        // 8
#define NBLK   (NPTS / WARPS)     // 24 blocks

// Fixed-point scale for deterministic integer accumulation.
#define SCALE_MAIN 4194304.0      // 2^22; per-block sum < 2^31, 24 blocks < 2^36

// Arrival tag packed into the accumulator's high bits: one atomicAdd serves as
// both merge and arrival counter. Low 58 bits: fixed-point sum (< 2^36, and
// always non-negative -> no carry into the tag field). Bits 58+: arrival count.
#define ARRIVE_TAG (1ULL << 58)
#define SUM_MASK   (ARRIVE_TAG - 1ULL)

// Zero at module load; the elected last block resets it after reading, so every
// launch / graph replay sees identical initial state -> deterministic.
__device__ unsigned long long g_acc;

__device__ __forceinline__ float sigmoidf_(float x) {
    return __frcp_rn(1.0f + __expf(-x));
}

// ---------------------------------------------------------------------------
// 24 blocks x 256 threads; warp = point. Per-point sums quantized to fixed
// point (order-independent), integer-summed in smem, merged with ONE
// tagged atomicAdd per block. The block whose atomicAdd return shows 23 prior
// arrivals is last: its (old + own) low bits ARE the final total -> no second
// atomic, no read-back, no threadfence on anyone's critical path.
// ---------------------------------------------------------------------------
__global__ __launch_bounds__(NTHR)
void loss_fused(const float* __restrict__ pre_hough,
                const float* __restrict__ gt_hough,
                const int*   __restrict__ in_pre_points,
                const int*   __restrict__ gt_points,
                float*       __restrict__ out)
{
    __shared__ long long s_q[WARPS];
    __shared__ int       s_fb;      // 1 => this block runs the fallback
    __shared__ double    s_red[NTHR];

    const int tid  = threadIdx.x;
    const int warp = tid >> 5;
    const int lane = tid & 31;
    const int p    = blockIdx.x * WARPS + warp;   // 0..191
    const int b    = p / L_;
    const int l    = p - b * L_;

    if (tid == 0) s_fb = 0;

    // ---- Point prep, redundantly per thread (broadcast loads; sort only
    //      when its effect is observable) ----
    int X, Y;
    float W;
    {
        const int4* pp = (const int4*)(in_pre_points + b * (L_ * 2));
        const int4 v0 = pp[0], v1 = pp[1], v2 = pp[2];
        const int2 g  = ((const int2*)(gt_points + b * (L_ * 2)))[l];
        int px[L_] = { v0.x, v0.z, v1.x, v1.z, v2.x, v2.z };
        int py[L_] = { v0.y, v0.w, v1.y, v1.w, v2.y, v2.w };

        // Sort is observable only if some pre-point is invalid (weight-mask
        // position) or some gt point is invalid (sorted values consumed).
        // gt validity for OTHER lanes' points matters, so check all 6.
        const int4* ggv = (const int4*)(gt_points + b * (L_ * 2));
        const int4 w0 = ggv[0], w1 = ggv[1], w2 = ggv[2];
        const int minpx = min(min(min(px[0], px[1]), min(px[2], px[3])), min(px[4], px[5]));
        const int mingx = min(min(min(w0.x, w0.z), min(w1.x, w1.z)), min(w2.x, w2.z));
        if ((minpx < 0) | (mingx < 0)) {
            // 32-bit keys: valid key <= 999*10000+999 < 2^30 = BIG_KEY < 2^31.
            int key[L_];
            #pragma unroll
            for (int i = 0; i < L_; ++i)
                key[i] = (px[i] < 0) ? (1 << 30) : px[i] * 10000 + py[i];
            // Stable insertion sort (matches stable argsort).
            #pragma unroll
            for (int i = 1; i < L_; ++i) {
                int kk = key[i], kx = px[i], ky = py[i];
                int j = i - 1;
                while (j >= 0 && key[j] > kk) {
                    key[j + 1] = key[j]; px[j + 1] = px[j]; py[j + 1] = py[j];
                    --j;
                }
                key[j + 1] = kk; px[j + 1] = kx; py[j + 1] = ky;
            }
        }

        const bool use_gt   = (g.x >= 0);
        const bool one_inv  = (px[l] < 0) || (g.x < 0);
        const bool both_inv = (px[l] < 0) && (g.x < 0);
        X = use_gt ? g.x : px[l];
        Y = use_gt ? g.y : py[l];
        W = both_inv ? 0.0f : (one_inv ? 10.0f : 1.0f) / (float)(RAD * RAD);
    }

    // ---- Gather: lane covers cells lane+32*it (121 cells, MLP=8) ----
    float vp[4], vg[4];
    bool  ok[4];
    #pragma unroll
    for (int it = 0; it < 4; ++it) {
        const int idx = lane + it * 32;
        const int di  = idx / WIN - RAD;
        const int dj  = idx % WIN - RAD;
        const int xi  = X + di;
        const int yi  = Y + dj;
        ok[it] = (idx < NWIN) & (xi >= 0) & (xi < R_) & (yi >= 0) & (yi < A_);
        const size_t off = (size_t)b * NELEM + (size_t)(ok[it] ? xi : 0) * R_ + (ok[it] ? yi : 0);
        vp[it] = pre_hough[off];
        vg[it] = gt_hough[off];
    }
    float acc = 0.0f;
    #pragma unroll
    for (int it = 0; it < 4; ++it)
        if (ok[it]) acc += fabsf(sigmoidf_(vp[it]) - vg[it]);

    // ---- Warp reduce (deterministic), quantize per point ----
    #pragma unroll
    for (int off = 16; off > 0; off >>= 1)
        acc += __shfl_down_sync(0xffffffffu, acc, off);
    if (lane == 0)
        s_q[warp] = __double2ll_rn((double)(acc * W) * SCALE_MAIN);
    __syncthreads();

    // ---- Single tagged atomic: merge + arrival count in one op ----
    if (tid == 0) {
        long long qs = 0;
        #pragma unroll
        for (int w = 0; w < WARPS; ++w) qs += s_q[w];
        const unsigned long long mine = (unsigned long long)qs + ARRIVE_TAG;
        const unsigned long long old  = atomicAdd(&g_acc, mine);
        if ((old >> 58) == (unsigned long long)(NBLK - 1)) {
            // Last arrival: old already holds everyone else's sums.
            const unsigned long long total_q = (old + mine) & SUM_MASK;
            g_acc = 0ULL;               // restore invariant for next replay
            const float total = (float)((double)total_q / SCALE_MAIN);
            if (total != 0.0f) {
                out[0] = total / (float)B_;
            } else {
                s_fb = 1;               // this block alone runs the fallback
            }
        }
    }
    __syncthreads();

    // ---- Fallback: ONE block, only when total == 0 (never on this data) ----
    if (s_fb) {
        double d = 0.0;
        for (long long i = tid; i < TOTAL_ELEMS; i += NTHR)
            d += (double)fabsf(1.0f / (1.0f + expf(-pre_hough[i])) - gt_hough[i]);
        s_red[tid] = d;
        __syncthreads();
        for (int off = NTHR / 2; off > 0; off >>= 1) {
            if (tid < off) s_red[tid] += s_red[tid + off];
            __syncthreads();
        }
        if (tid == 0)
            out[0] = (float)(s_red[0] / (double)TOTAL_ELEMS);
    }
}

// ---------------------------------------------------------------------------
extern "C" void kernel_launch(void* const* d_in, const int* in_sizes, int n_in,
                              void* d_out, int out_size)
{
    const float* pre_hough     = (const float*)d_in[0];
    const float* gt_hough      = (const float*)d_in[1];
    const int*   in_pre_points = (const int*)d_in[2];
    const int*   gt_points     = (const int*)d_in[3];
    float*       out           = (float*)d_out;

    loss_fused<<<NBLK, NTHR>>>(pre_hough, gt_hough, in_pre_points, gt_points, out);
}